// round 14
// baseline (speedup 1.0000x reference)
#include <cuda_runtime.h>
#include <cstdint>
#include <cstddef>

// Problem constants: B=8, T=256, D=512, S=256, V=32000, L=2
#define NB 8
#define NT 256
#define ND 512
#define NS 256
#define NV 32000
#define NL 2
#define NROWS (NB * NT)   // 2048
#define NV4 (NV / 4)      // 8000

// ---------------- scratch (static device globals; no runtime allocation) ----
__device__ __align__(16) float g_Y[NROWS * ND];      // X @ enc_W + enc_b
__device__ __align__(16) float g_bu[NROWS * ND];     // encoder spikes (slow path)
__device__ __align__(16) float g_preds[NROWS * ND];  // fallback-path preds
__device__ __align__(16) float g_r[NV];              // shared logits row
__device__ unsigned int g_ymax[ND];                  // per-channel max |y| (uint bits)
__device__ int g_count;                              // total encoder spikes
__device__ int g_bad;                                // nonzero bias / bad threshold
__device__ int g_need;                               // spike bound violated -> need scan

// ---------------- init + invariant checks (single block) ---------------------
__global__ void k_init_check(const float* __restrict__ gen_b, const float* __restrict__ inf_b,
                             const float* __restrict__ ne_b, const float* __restrict__ ns_b,
                             const float* __restrict__ gen_thr, const float* __restrict__ inf_thr) {
    const int tid = threadIdx.x;  // 512 threads
    if (tid == 0) { g_count = 0; g_bad = 0; g_need = 0; }
    g_ymax[tid] = 0u;
    int bad = 0;
    for (int i = tid; i < NL * ND; i += blockDim.x) {
        if (gen_b[i] != 0.f || ne_b[i] != 0.f || !(gen_thr[i] > 0.f)) bad = 1;
    }
    for (int i = tid; i < NL * NS; i += blockDim.x) {
        if (inf_b[i] != 0.f || ns_b[i] != 0.f || !(inf_thr[i] > 0.f)) bad = 1;
    }
    if (bad) atomicOr(&g_bad, 1);
}

// ---------------- Y = (tok_emb[ids] + pos_emb) @ enc_W + enc_b --------------
// Tiled SGEMM: BM=64, BN=64, BK=16, 256 threads, 4x4 register tile.
// Epilogue also folds the per-channel max|Y| reduction (fused k_ymax).
__global__ void k_gemm_enc(const int* __restrict__ ids,
                           const float* __restrict__ tok,
                           const float* __restrict__ pos,
                           const float* __restrict__ W,
                           const float* __restrict__ enc_b) {
    __shared__ __align__(16) float As[16][64];
    __shared__ __align__(16) float Bs[16][64];
    const int bm = blockIdx.y * 64;
    const int bn = blockIdx.x * 64;
    const int tid = threadIdx.x;
    const int tr = tid >> 4;
    const int tc = tid & 15;

    const int lr  = tid >> 2;
    const int lk4 = tid & 3;
    const int arow = bm + lr;
    const int aid  = ids[arow];
    const int at   = arow & (NT - 1);
    const float* tokp = tok + (size_t)aid * ND;
    const float* posp = pos + (size_t)at  * ND;
    const int lkb = tid >> 4;
    const int ln4 = tid & 15;

    float acc[4][4];
#pragma unroll
    for (int i = 0; i < 4; i++)
#pragma unroll
        for (int j = 0; j < 4; j++) acc[i][j] = 0.f;

    for (int k0 = 0; k0 < ND; k0 += 16) {
        float4 av = *(const float4*)(tokp + k0 + lk4 * 4);
        float4 pv = *(const float4*)(posp + k0 + lk4 * 4);
        As[lk4 * 4 + 0][lr] = av.x + pv.x;
        As[lk4 * 4 + 1][lr] = av.y + pv.y;
        As[lk4 * 4 + 2][lr] = av.z + pv.z;
        As[lk4 * 4 + 3][lr] = av.w + pv.w;
        float4 wv = *(const float4*)(W + (size_t)(k0 + lkb) * ND + bn + ln4 * 4);
        *(float4*)&Bs[lkb][ln4 * 4] = wv;
        __syncthreads();
#pragma unroll
        for (int kk = 0; kk < 16; kk++) {
            float a[4], b[4];
            *(float4*)a = *(const float4*)&As[kk][tr * 4];
            *(float4*)b = *(const float4*)&Bs[kk][tc * 4];
#pragma unroll
            for (int i = 0; i < 4; i++)
#pragma unroll
                for (int j = 0; j < 4; j++) acc[i][j] += a[i] * b[j];
        }
        __syncthreads();
    }
    float4 eb = *(const float4*)(enc_b + bn + tc * 4);
    float cmax[4] = {0.f, 0.f, 0.f, 0.f};
#pragma unroll
    for (int i = 0; i < 4; i++) {
        float4 o;
        o.x = acc[i][0] + eb.x; o.y = acc[i][1] + eb.y;
        o.z = acc[i][2] + eb.z; o.w = acc[i][3] + eb.w;
        cmax[0] = fmaxf(cmax[0], fabsf(o.x));
        cmax[1] = fmaxf(cmax[1], fabsf(o.y));
        cmax[2] = fmaxf(cmax[2], fabsf(o.z));
        cmax[3] = fmaxf(cmax[3], fabsf(o.w));
        *(float4*)(g_Y + (size_t)(bm + tr * 4 + i) * ND + bn + tc * 4) = o;
    }
    // fused per-channel max|Y| (values >= 0 so uint-bit ordering is valid)
#pragma unroll
    for (int j = 0; j < 4; j++)
        atomicMax(&g_ymax[bn + tc * 4 + j], __float_as_uint(cmax[j]));
}

// Sufficient no-spike condition per channel: max|y| / (1-decay) < thr.
// (Reset-to-zero only shrinks |membrane|: |m_t| <= max|y| * sum decay^k.)
__global__ void k_gate(const float* __restrict__ tau, const float* __restrict__ thr) {
    const int d = threadIdx.x;  // 512 threads
    float decay = expf(-1.f / fmaxf(tau[d], 1.f));
    float ymax = __uint_as_float(g_ymax[d]);
    float om = 1.f - decay;
    int need = (!(om > 0.f)) || (ymax >= thr[d] * om);
    if (need) atomicOr(&g_need, 1);
}

// ---------------- encoder LIF scan (honest; runs only when needed) ----------
__global__ void k_enc_scan(const float* __restrict__ tau, const float* __restrict__ thr) {
    if (!(g_need || g_bad)) return;
    const int idx = blockIdx.x * blockDim.x + threadIdx.x;
    const int b = idx >> 9;
    const int d = idx & (ND - 1);
    const float decay = expf(-1.f / fmaxf(tau[d], 1.f));
    const float th = thr[d];
    const float* y  = g_Y  + ((size_t)b << 17) + d;
    float*       bu = g_bu + ((size_t)b << 17) + d;
    float m = 0.f;
    int cnt = 0;
#pragma unroll 4
    for (int t = 0; t < NT; t++) {
        m = m * decay + y[(size_t)t << 9];
        float s = (m - th >= 0.f) ? 1.f : 0.f;
        cnt += (int)s;
        bu[(size_t)t << 9] = s;
        m *= (1.f - s);
    }
#pragma unroll
    for (int o = 16; o; o >>= 1) cnt += __shfl_down_sync(0xffffffffu, cnt, o);
    if ((threadIdx.x & 31) == 0 && cnt) atomicAdd(&g_count, cnt);
}

// ---------------- block-sum helper ------------------------------------------
template <int NTH>
__device__ __forceinline__ float blk_sum(float v, float* red) {
    const int tid = threadIdx.x;
#pragma unroll
    for (int o = 16; o; o >>= 1) v += __shfl_down_sync(0xffffffffu, v, o);
    if ((tid & 31) == 0) red[tid >> 5] = v;
    __syncthreads();
    if (tid == 0) {
        float r = 0.f;
#pragma unroll
        for (int w = 0; w < NTH / 32; w++) r += red[w];
        red[0] = r;
    }
    __syncthreads();
    float r = red[0];
    __syncthreads();
    return r;
}

// ---------------- full scan fallback (runs only if invariants broken) -------
__global__ void k_slow_scan(const float* __restrict__ gen_W, const float* __restrict__ gen_b,
                            const float* __restrict__ gen_tau, const float* __restrict__ gen_thr,
                            const float* __restrict__ inf_W, const float* __restrict__ inf_b,
                            const float* __restrict__ inf_tau, const float* __restrict__ inf_thr,
                            const float* __restrict__ ne_g, const float* __restrict__ ne_b,
                            const float* __restrict__ ns_g, const float* __restrict__ ns_b) {
    if (g_count == 0 && g_bad == 0) return;

    __shared__ float st[NL][NS], mg[NL][ND], mi[NL][NS];
    __shared__ float bu[ND], err[ND], pr[ND], su[NS];
    __shared__ float red[16];
    const int b = blockIdx.x;
    const int tid = threadIdx.x;

    if (tid < NS) { st[0][tid] = 0.f; st[1][tid] = 0.f; mi[0][tid] = 0.f; mi[1][tid] = 0.f; }
    mg[0][tid] = 0.f; mg[1][tid] = 0.f;
    __syncthreads();

    for (int t = 0; t < NT; t++) {
        bu[tid] = g_bu[(((size_t)b * NT + t) << 9) + tid];
        __syncthreads();
        for (int j = 0; j < NL; j++) {
            {
                float x = gen_b[j * ND + tid];
                const float* W = gen_W + (size_t)j * NS * ND + tid;
                for (int s = 0; s < NS; s++) x += st[j][s] * W[(size_t)s * ND];
                float dec = expf(-1.f / fmaxf(gen_tau[j * ND + tid], 1.f));
                float m = mg[j][tid] * dec + x;
                float sp = (m - gen_thr[j * ND + tid] >= 0.f) ? 1.f : 0.f;
                pr[tid] = sp;
                mg[j][tid] = m * (1.f - sp);
            }
            __syncthreads();
            {
                float v = bu[tid] - pr[tid];
                float mu = blk_sum<512>(v, red) * (1.f / ND);
                float d = v - mu;
                float var = blk_sum<512>(d * d, red) * (1.f / ND);
                err[tid] = d * rsqrtf(var + 1e-5f) * ne_g[j * ND + tid] + ne_b[j * ND + tid];
            }
            __syncthreads();
            if (tid < NS) {
                float x = inf_b[j * NS + tid];
                const float* W = inf_W + (size_t)j * ND * NS + tid;
                for (int d = 0; d < ND; d++) x += err[d] * W[(size_t)d * NS];
                float dec = expf(-1.f / fmaxf(inf_tau[j * NS + tid], 1.f));
                float m = mi[j][tid] * dec + x;
                float sp = (m - inf_thr[j * NS + tid] >= 0.f) ? 1.f : 0.f;
                su[tid] = sp;
                mi[j][tid] = m * (1.f - sp);
            }
            __syncthreads();
            {
                float v = (tid < NS) ? (st[j][tid] + su[tid]) : 0.f;
                float mu = blk_sum<512>(v, red) * (1.f / NS);
                float d = (tid < NS) ? (v - mu) : 0.f;
                float var = blk_sum<512>(d * d, red) * (1.f / NS);
                if (tid < NS)
                    st[j][tid] = d * rsqrtf(var + 1e-5f) * ns_g[j * NS + tid] + ns_b[j * NS + tid];
            }
            __syncthreads();
            bu[tid] = err[tid];
            __syncthreads();
        }
        {
            const int j = NL - 1;
            float x = gen_b[j * ND + tid];
            const float* W = gen_W + (size_t)j * NS * ND + tid;
            for (int s = 0; s < NS; s++) x += st[j][s] * W[(size_t)s * ND];
            float dec = expf(-1.f / fmaxf(gen_tau[j * ND + tid], 1.f));
            float m = mg[j][tid] * dec + x;
            float sp = (m - gen_thr[j * ND + tid] >= 0.f) ? 1.f : 0.f;
            g_preds[(((size_t)b * NT + t) << 9) + tid] = sp;
            mg[j][tid] = m * (1.f - sp);
            pr[tid] = -sp;
        }
        __syncthreads();
        {
            const int j = NL - 1;
            float v = pr[tid];
            float mu = blk_sum<512>(v, red) * (1.f / ND);
            float d = v - mu;
            float var = blk_sum<512>(d * d, red) * (1.f / ND);
            err[tid] = d * rsqrtf(var + 1e-5f) * ne_g[j * ND + tid] + ne_b[j * ND + tid];
        }
        __syncthreads();
        if (tid < NS) {
            const int j = NL - 1;
            float x = inf_b[j * NS + tid];
            const float* W = inf_W + (size_t)j * ND * NS + tid;
            for (int d = 0; d < ND; d++) x += err[d] * W[(size_t)d * NS];
            float dec = expf(-1.f / fmaxf(inf_tau[j * NS + tid], 1.f));
            float m = mi[j][tid] * dec + x;
            float sp = (m - inf_thr[j * NS + tid] >= 0.f) ? 1.f : 0.f;
            mi[j][tid] = m * (1.f - sp);
        }
        __syncthreads();
    }
}

// ---------------- shared logits row for all-zero pred rows ------------------
__global__ void k_compute_r(const float* __restrict__ out_b,
                            const float* __restrict__ out_W,
                            const float* __restrict__ out_b2) {
    __shared__ float vals[ND];
    __shared__ int nz;
    const int tid = threadIdx.x;
    if (tid == 0) nz = 0;
    __syncthreads();
    for (int d = tid; d < ND; d += blockDim.x) {
        float x = out_b[d];
        float v = 0.5f * x * (1.f + erff(x * 0.70710678118654752f));
        vals[d] = v;
        if (v != 0.f) atomicOr(&nz, 1);
    }
    __syncthreads();
    const int v0 = blockIdx.x * blockDim.x + tid;
    if (v0 >= NV) return;
    float acc = out_b2[v0];
    if (nz) {
        for (int d = 0; d < ND; d++) acc += vals[d] * out_W[(size_t)d * NV + v0];
    }
    g_r[v0] = acc;
}

// ---------------- fast broadcast: 16 rows per block, read g_r once ----------
__global__ void k_final_fast(float* __restrict__ out) {
    if (g_count != 0 || g_bad != 0) return;
    const int c = blockIdx.x * blockDim.x + threadIdx.x;
    if (c >= NV4) return;
    const float4 v = ((const float4*)g_r)[c];
    float4* o = (float4*)out + (size_t)blockIdx.y * 16 * NV4 + c;
#pragma unroll
    for (int r = 0; r < 16; r++) o[(size_t)r * NV4] = v;
}

// ---------------- general per-row output (gated) -----------------------------
__global__ void k_final_slow(float* __restrict__ out,
                             const float* __restrict__ out_g, const float* __restrict__ out_b,
                             const float* __restrict__ out_W, const float* __restrict__ out_b2) {
    if (g_count == 0 && g_bad == 0) return;
    const int row = blockIdx.x;
    const int tid = threadIdx.x;
    float* orow = out + (size_t)row * NV;
    __shared__ float vals[ND];
    __shared__ float red[16];
    float p0 = g_preds[(size_t)row * ND + tid];
    float p1 = g_preds[(size_t)row * ND + tid + 256];
    float mu = blk_sum<256>(p0 + p1, red) * (1.f / ND);
    float d0 = p0 - mu, d1 = p1 - mu;
    float var = blk_sum<256>(d0 * d0 + d1 * d1, red) * (1.f / ND);
    float rs = rsqrtf(var + 1e-5f);
    {
        float x0 = d0 * rs * out_g[tid] + out_b[tid];
        float x1 = d1 * rs * out_g[tid + 256] + out_b[tid + 256];
        vals[tid]       = 0.5f * x0 * (1.f + erff(x0 * 0.70710678118654752f));
        vals[tid + 256] = 0.5f * x1 * (1.f + erff(x1 * 0.70710678118654752f));
    }
    __syncthreads();
    for (int v = tid; v < NV; v += blockDim.x) {
        float acc = out_b2[v];
        for (int d = 0; d < ND; d++) acc += vals[d] * out_W[(size_t)d * NV + v];
        orow[v] = acc;
    }
}

// ---------------- launch -----------------------------------------------------
extern "C" void kernel_launch(void* const* d_in, const int* in_sizes, int n_in,
                              void* d_out, int out_size) {
    const int*   ids     = (const int*)d_in[0];
    const float* tok     = (const float*)d_in[1];
    const float* pos     = (const float*)d_in[2];
    const float* enc_W   = (const float*)d_in[3];
    const float* enc_b   = (const float*)d_in[4];
    const float* enc_tau = (const float*)d_in[5];
    const float* enc_thr = (const float*)d_in[6];
    const float* gen_W   = (const float*)d_in[7];
    const float* gen_b   = (const float*)d_in[8];
    const float* gen_tau = (const float*)d_in[9];
    const float* gen_thr = (const float*)d_in[10];
    const float* inf_W   = (const float*)d_in[11];
    const float* inf_b   = (const float*)d_in[12];
    const float* inf_tau = (const float*)d_in[13];
    const float* inf_thr = (const float*)d_in[14];
    const float* ne_g    = (const float*)d_in[15];
    const float* ne_b    = (const float*)d_in[16];
    const float* ns_g    = (const float*)d_in[17];
    const float* ns_b    = (const float*)d_in[18];
    const float* out_g   = (const float*)d_in[19];
    const float* out_b   = (const float*)d_in[20];
    const float* out_W   = (const float*)d_in[21];
    const float* out_b2  = (const float*)d_in[22];
    float* out = (float*)d_out;

    k_init_check<<<1, 512>>>(gen_b, inf_b, ne_b, ns_b, gen_thr, inf_thr);
    k_gemm_enc<<<dim3(ND / 64, NROWS / 64), 256>>>(ids, tok, pos, enc_W, enc_b);
    k_gate<<<1, 512>>>(enc_tau, enc_thr);
    k_enc_scan<<<(NB * ND) / 256, 256>>>(enc_tau, enc_thr);
    k_slow_scan<<<NB, 512>>>(gen_W, gen_b, gen_tau, gen_thr,
                             inf_W, inf_b, inf_tau, inf_thr,
                             ne_g, ne_b, ns_g, ns_b);
    k_compute_r<<<(NV + 255) / 256, 256>>>(out_b, out_W, out_b2);
    k_final_fast<<<dim3((NV4 + 255) / 256, NROWS / 16), 256>>>(out);
    k_final_slow<<<NROWS, 256>>>(out, out_g, out_b, out_W, out_b2);
}

// round 15
// speedup vs baseline: 1.2033x; 1.2033x over previous
#include <cuda_runtime.h>
#include <cstdint>
#include <cstddef>

// Problem constants: B=8, T=256, D=512, S=256, V=32000, L=2
#define NB 8
#define NT 256
#define ND 512
#define NS 256
#define NV 32000
#define NL 2
#define NROWS (NB * NT)   // 2048
#define NV4 (NV / 4)      // 8000

// ---------------- scratch (static device globals; no runtime allocation) ----
__device__ __align__(16) float g_Y[NROWS * ND];      // X @ enc_W + enc_b
__device__ __align__(16) float g_preds[NROWS * ND];  // fallback-path preds
__device__ unsigned int g_ymax[ND];                  // per-channel max |y| (uint bits)
__device__ int g_count;                              // total encoder spikes
__device__ int g_bad;                                // nonzero bias / bad threshold

// ---------------- init + invariant checks (single block) ---------------------
__global__ void k_init_check(const float* __restrict__ gen_b, const float* __restrict__ inf_b,
                             const float* __restrict__ ne_b, const float* __restrict__ ns_b,
                             const float* __restrict__ gen_thr, const float* __restrict__ inf_thr) {
    const int tid = threadIdx.x;  // 512 threads
    if (tid == 0) { g_count = 0; g_bad = 0; }
    g_ymax[tid] = 0u;
    int bad = 0;
    for (int i = tid; i < NL * ND; i += blockDim.x) {
        if (gen_b[i] != 0.f || ne_b[i] != 0.f || !(gen_thr[i] > 0.f)) bad = 1;
    }
    for (int i = tid; i < NL * NS; i += blockDim.x) {
        if (inf_b[i] != 0.f || ns_b[i] != 0.f || !(inf_thr[i] > 0.f)) bad = 1;
    }
    if (bad) atomicOr(&g_bad, 1);
}

// ---------------- Y = (tok_emb[ids] + pos_emb) @ enc_W + enc_b --------------
// Tiled SGEMM: BM=64, BN=64, BK=16, 256 threads, 4x4 register tile.
// Epilogue folds per-channel max|Y|: in-block smem reduction first, then only
// 64 atomics per block (32 per address grid-wide) -> no L2 atomic tail.
__global__ void k_gemm_enc(const int* __restrict__ ids,
                           const float* __restrict__ tok,
                           const float* __restrict__ pos,
                           const float* __restrict__ W,
                           const float* __restrict__ enc_b) {
    __shared__ __align__(16) float As[16][64];
    __shared__ __align__(16) float Bs[16][64];
    const int bm = blockIdx.y * 64;
    const int bn = blockIdx.x * 64;
    const int tid = threadIdx.x;
    const int tr = tid >> 4;
    const int tc = tid & 15;

    const int lr  = tid >> 2;
    const int lk4 = tid & 3;
    const int arow = bm + lr;
    const int aid  = ids[arow];
    const int at   = arow & (NT - 1);
    const float* tokp = tok + (size_t)aid * ND;
    const float* posp = pos + (size_t)at  * ND;
    const int lkb = tid >> 4;
    const int ln4 = tid & 15;

    float acc[4][4];
#pragma unroll
    for (int i = 0; i < 4; i++)
#pragma unroll
        for (int j = 0; j < 4; j++) acc[i][j] = 0.f;

    for (int k0 = 0; k0 < ND; k0 += 16) {
        float4 av = *(const float4*)(tokp + k0 + lk4 * 4);
        float4 pv = *(const float4*)(posp + k0 + lk4 * 4);
        As[lk4 * 4 + 0][lr] = av.x + pv.x;
        As[lk4 * 4 + 1][lr] = av.y + pv.y;
        As[lk4 * 4 + 2][lr] = av.z + pv.z;
        As[lk4 * 4 + 3][lr] = av.w + pv.w;
        float4 wv = *(const float4*)(W + (size_t)(k0 + lkb) * ND + bn + ln4 * 4);
        *(float4*)&Bs[lkb][ln4 * 4] = wv;
        __syncthreads();
#pragma unroll
        for (int kk = 0; kk < 16; kk++) {
            float a[4], b[4];
            *(float4*)a = *(const float4*)&As[kk][tr * 4];
            *(float4*)b = *(const float4*)&Bs[kk][tc * 4];
#pragma unroll
            for (int i = 0; i < 4; i++)
#pragma unroll
                for (int j = 0; j < 4; j++) acc[i][j] += a[i] * b[j];
        }
        __syncthreads();
    }
    float4 eb = *(const float4*)(enc_b + bn + tc * 4);
    float cmax[4] = {0.f, 0.f, 0.f, 0.f};
#pragma unroll
    for (int i = 0; i < 4; i++) {
        float4 o;
        o.x = acc[i][0] + eb.x; o.y = acc[i][1] + eb.y;
        o.z = acc[i][2] + eb.z; o.w = acc[i][3] + eb.w;
        cmax[0] = fmaxf(cmax[0], fabsf(o.x));
        cmax[1] = fmaxf(cmax[1], fabsf(o.y));
        cmax[2] = fmaxf(cmax[2], fabsf(o.z));
        cmax[3] = fmaxf(cmax[3], fabsf(o.w));
        *(float4*)(g_Y + (size_t)(bm + tr * 4 + i) * ND + bn + tc * 4) = o;
    }
    // in-block reduction of cmax over the 16 tr-rows, then 64 atomics/block
    float* part = &As[0][0];  // reuse: 8 warps * 64 channels = 512 floats
#pragma unroll
    for (int j = 0; j < 4; j++)
        cmax[j] = fmaxf(cmax[j], __shfl_xor_sync(0xffffffffu, cmax[j], 16));
    const int w = tid >> 5;
    if ((tid & 16) == 0) {
#pragma unroll
        for (int j = 0; j < 4; j++) part[w * 64 + tc * 4 + j] = cmax[j];
    }
    __syncthreads();
    if (tid < 64) {
        float mx = 0.f;
#pragma unroll
        for (int ww = 0; ww < 8; ww++) mx = fmaxf(mx, part[ww * 64 + tid]);
        atomicMax(&g_ymax[bn + tid], __float_as_uint(mx));
    }
}

// ---------------- encoder LIF spike detection (gate fused) -------------------
// Sufficient no-spike bound per channel: max|y| / (1-decay) < thr
// (reset-to-zero only shrinks |membrane|: |m_t| <= max|y| * sum decay^k).
// Threads whose channel passes the bound skip; others run the honest scan and
// count spikes. No bu stores: the slow path recomputes the encoder inline.
__global__ void k_enc_scan(const float* __restrict__ tau, const float* __restrict__ thr) {
    const int idx = blockIdx.x * blockDim.x + threadIdx.x;
    const int b = idx >> 9;
    const int d = idx & (ND - 1);
    const float decay = expf(-1.f / fmaxf(tau[d], 1.f));
    const float th = thr[d];
    const float om = 1.f - decay;
    const float ymax = __uint_as_float(g_ymax[d]);
    const bool need = (!(om > 0.f)) || (ymax >= th * om);
    if (!need) return;  // provably spike-free channel
    const float* y = g_Y + ((size_t)b << 17) + d;
    float m = 0.f;
    int cnt = 0;
#pragma unroll 4
    for (int t = 0; t < NT; t++) {
        m = m * decay + y[(size_t)t << 9];
        float s = (m - th >= 0.f) ? 1.f : 0.f;
        cnt += (int)s;
        m *= (1.f - s);
    }
    if (cnt) atomicAdd(&g_count, cnt);
}

// ---------------- block-sum helper ------------------------------------------
template <int NTH>
__device__ __forceinline__ float blk_sum(float v, float* red) {
    const int tid = threadIdx.x;
#pragma unroll
    for (int o = 16; o; o >>= 1) v += __shfl_down_sync(0xffffffffu, v, o);
    if ((tid & 31) == 0) red[tid >> 5] = v;
    __syncthreads();
    if (tid == 0) {
        float r = 0.f;
#pragma unroll
        for (int w = 0; w < NTH / 32; w++) r += red[w];
        red[0] = r;
    }
    __syncthreads();
    float r = red[0];
    __syncthreads();
    return r;
}

// ---------------- full scan fallback (runs only if invariants broken) -------
// One CTA per batch row; recomputes encoder LIF inline from g_Y (tid = d).
__global__ void k_slow_scan(const float* __restrict__ enc_tau, const float* __restrict__ enc_thr,
                            const float* __restrict__ gen_W, const float* __restrict__ gen_b,
                            const float* __restrict__ gen_tau, const float* __restrict__ gen_thr,
                            const float* __restrict__ inf_W, const float* __restrict__ inf_b,
                            const float* __restrict__ inf_tau, const float* __restrict__ inf_thr,
                            const float* __restrict__ ne_g, const float* __restrict__ ne_b,
                            const float* __restrict__ ns_g, const float* __restrict__ ns_b) {
    if (g_count == 0 && g_bad == 0) return;

    __shared__ float st[NL][NS], mg[NL][ND], mi[NL][NS];
    __shared__ float bu[ND], err[ND], pr[ND], su[NS];
    __shared__ float red[16];
    const int b = blockIdx.x;
    const int tid = threadIdx.x;  // 0..511

    if (tid < NS) { st[0][tid] = 0.f; st[1][tid] = 0.f; mi[0][tid] = 0.f; mi[1][tid] = 0.f; }
    mg[0][tid] = 0.f; mg[1][tid] = 0.f;
    const float enc_dec = expf(-1.f / fmaxf(enc_tau[tid], 1.f));
    const float enc_th  = enc_thr[tid];
    float m_enc = 0.f;
    __syncthreads();

    for (int t = 0; t < NT; t++) {
        // inline encoder LIF (exact recurrence)
        {
            float yv = g_Y[(((size_t)b * NT + t) << 9) + tid];
            m_enc = m_enc * enc_dec + yv;
            float s = (m_enc - enc_th >= 0.f) ? 1.f : 0.f;
            bu[tid] = s;
            m_enc *= (1.f - s);
        }
        __syncthreads();
        for (int j = 0; j < NL; j++) {
            {
                float x = gen_b[j * ND + tid];
                const float* W = gen_W + (size_t)j * NS * ND + tid;
                for (int s = 0; s < NS; s++) x += st[j][s] * W[(size_t)s * ND];
                float dec = expf(-1.f / fmaxf(gen_tau[j * ND + tid], 1.f));
                float m = mg[j][tid] * dec + x;
                float sp = (m - gen_thr[j * ND + tid] >= 0.f) ? 1.f : 0.f;
                pr[tid] = sp;
                mg[j][tid] = m * (1.f - sp);
            }
            __syncthreads();
            {
                float v = bu[tid] - pr[tid];
                float mu = blk_sum<512>(v, red) * (1.f / ND);
                float d = v - mu;
                float var = blk_sum<512>(d * d, red) * (1.f / ND);
                err[tid] = d * rsqrtf(var + 1e-5f) * ne_g[j * ND + tid] + ne_b[j * ND + tid];
            }
            __syncthreads();
            if (tid < NS) {
                float x = inf_b[j * NS + tid];
                const float* W = inf_W + (size_t)j * ND * NS + tid;
                for (int d = 0; d < ND; d++) x += err[d] * W[(size_t)d * NS];
                float dec = expf(-1.f / fmaxf(inf_tau[j * NS + tid], 1.f));
                float m = mi[j][tid] * dec + x;
                float sp = (m - inf_thr[j * NS + tid] >= 0.f) ? 1.f : 0.f;
                su[tid] = sp;
                mi[j][tid] = m * (1.f - sp);
            }
            __syncthreads();
            {
                float v = (tid < NS) ? (st[j][tid] + su[tid]) : 0.f;
                float mu = blk_sum<512>(v, red) * (1.f / NS);
                float d = (tid < NS) ? (v - mu) : 0.f;
                float var = blk_sum<512>(d * d, red) * (1.f / NS);
                if (tid < NS)
                    st[j][tid] = d * rsqrtf(var + 1e-5f) * ns_g[j * NS + tid] + ns_b[j * NS + tid];
            }
            __syncthreads();
            bu[tid] = err[tid];
            __syncthreads();
        }
        {
            const int j = NL - 1;
            float x = gen_b[j * ND + tid];
            const float* W = gen_W + (size_t)j * NS * ND + tid;
            for (int s = 0; s < NS; s++) x += st[j][s] * W[(size_t)s * ND];
            float dec = expf(-1.f / fmaxf(gen_tau[j * ND + tid], 1.f));
            float m = mg[j][tid] * dec + x;
            float sp = (m - gen_thr[j * ND + tid] >= 0.f) ? 1.f : 0.f;
            g_preds[(((size_t)b * NT + t) << 9) + tid] = sp;
            mg[j][tid] = m * (1.f - sp);
            pr[tid] = -sp;
        }
        __syncthreads();
        {
            const int j = NL - 1;
            float v = pr[tid];
            float mu = blk_sum<512>(v, red) * (1.f / ND);
            float d = v - mu;
            float var = blk_sum<512>(d * d, red) * (1.f / ND);
            err[tid] = d * rsqrtf(var + 1e-5f) * ne_g[j * ND + tid] + ne_b[j * ND + tid];
        }
        __syncthreads();
        if (tid < NS) {
            const int j = NL - 1;
            float x = inf_b[j * NS + tid];
            const float* W = inf_W + (size_t)j * ND * NS + tid;
            for (int d = 0; d < ND; d++) x += err[d] * W[(size_t)d * NS];
            float dec = expf(-1.f / fmaxf(inf_tau[j * NS + tid], 1.f));
            float m = mi[j][tid] * dec + x;
            float sp = (m - inf_thr[j * NS + tid] >= 0.f) ? 1.f : 0.f;
            mi[j][tid] = m * (1.f - sp);
        }
        __syncthreads();
    }
}

// ---------------- fast output: fused row-compute + 32-row broadcast ----------
// All pred rows zero -> every output row == gelu(ln(0)=out_b) @ out_W + out_b2.
// Typical case (gelu(out_b) == 0): row is just out_b2, read directly.
__global__ void k_final_fast(float* __restrict__ out,
                             const float* __restrict__ out_b,
                             const float* __restrict__ out_W,
                             const float* __restrict__ out_b2) {
    if (g_count != 0 || g_bad != 0) return;  // slow kernel handles this case
    __shared__ float vals[ND];
    __shared__ int nz;
    const int tid = threadIdx.x;
    if (tid == 0) nz = 0;
    __syncthreads();
    for (int d = tid; d < ND; d += blockDim.x) {
        float x = out_b[d];
        float v = 0.5f * x * (1.f + erff(x * 0.70710678118654752f));
        vals[d] = v;
        if (v != 0.f) atomicOr(&nz, 1);
    }
    __syncthreads();
    const int c = blockIdx.x * blockDim.x + tid;  // float4 column index
    if (c >= NV4) return;
    float4 v = ((const float4*)out_b2)[c];
    if (nz) {
        for (int d = 0; d < ND; d++) {
            const float* wrow = out_W + (size_t)d * NV + c * 4;
            float g = vals[d];
            v.x += g * wrow[0]; v.y += g * wrow[1];
            v.z += g * wrow[2]; v.w += g * wrow[3];
        }
    }
    float4* o = (float4*)out + (size_t)blockIdx.y * 32 * NV4 + c;
#pragma unroll
    for (int r = 0; r < 32; r++) __stcs(&o[(size_t)r * NV4], v);
}

// ---------------- general per-row output (gated) -----------------------------
__global__ void k_final_slow(float* __restrict__ out,
                             const float* __restrict__ out_g, const float* __restrict__ out_b,
                             const float* __restrict__ out_W, const float* __restrict__ out_b2) {
    if (g_count == 0 && g_bad == 0) return;
    const int row = blockIdx.x;
    const int tid = threadIdx.x;
    float* orow = out + (size_t)row * NV;
    __shared__ float vals[ND];
    __shared__ float red[16];
    float p0 = g_preds[(size_t)row * ND + tid];
    float p1 = g_preds[(size_t)row * ND + tid + 256];
    float mu = blk_sum<256>(p0 + p1, red) * (1.f / ND);
    float d0 = p0 - mu, d1 = p1 - mu;
    float var = blk_sum<256>(d0 * d0 + d1 * d1, red) * (1.f / ND);
    float rs = rsqrtf(var + 1e-5f);
    {
        float x0 = d0 * rs * out_g[tid] + out_b[tid];
        float x1 = d1 * rs * out_g[tid + 256] + out_b[tid + 256];
        vals[tid]       = 0.5f * x0 * (1.f + erff(x0 * 0.70710678118654752f));
        vals[tid + 256] = 0.5f * x1 * (1.f + erff(x1 * 0.70710678118654752f));
    }
    __syncthreads();
    for (int v = tid; v < NV; v += blockDim.x) {
        float acc = out_b2[v];
        for (int d = 0; d < ND; d++) acc += vals[d] * out_W[(size_t)d * NV + v];
        orow[v] = acc;
    }
}

// ---------------- launch -----------------------------------------------------
extern "C" void kernel_launch(void* const* d_in, const int* in_sizes, int n_in,
                              void* d_out, int out_size) {
    const int*   ids     = (const int*)d_in[0];
    const float* tok     = (const float*)d_in[1];
    const float* pos     = (const float*)d_in[2];
    const float* enc_W   = (const float*)d_in[3];
    const float* enc_b   = (const float*)d_in[4];
    const float* enc_tau = (const float*)d_in[5];
    const float* enc_thr = (const float*)d_in[6];
    const float* gen_W   = (const float*)d_in[7];
    const float* gen_b   = (const float*)d_in[8];
    const float* gen_tau = (const float*)d_in[9];
    const float* gen_thr = (const float*)d_in[10];
    const float* inf_W   = (const float*)d_in[11];
    const float* inf_b   = (const float*)d_in[12];
    const float* inf_tau = (const float*)d_in[13];
    const float* inf_thr = (const float*)d_in[14];
    const float* ne_g    = (const float*)d_in[15];
    const float* ne_b    = (const float*)d_in[16];
    const float* ns_g    = (const float*)d_in[17];
    const float* ns_b    = (const float*)d_in[18];
    const float* out_g   = (const float*)d_in[19];
    const float* out_b   = (const float*)d_in[20];
    const float* out_W   = (const float*)d_in[21];
    const float* out_b2  = (const float*)d_in[22];
    float* out = (float*)d_out;

    k_init_check<<<1, 512>>>(gen_b, inf_b, ne_b, ns_b, gen_thr, inf_thr);
    k_gemm_enc<<<dim3(ND / 64, NROWS / 64), 256>>>(ids, tok, pos, enc_W, enc_b);
    k_enc_scan<<<(NB * ND) / 256, 256>>>(enc_tau, enc_thr);
    k_slow_scan<<<NB, 512>>>(enc_tau, enc_thr,
                             gen_W, gen_b, gen_tau, gen_thr,
                             inf_W, inf_b, inf_tau, inf_thr,
                             ne_g, ne_b, ns_g, ns_b);
    k_final_fast<<<dim3((NV4 + 255) / 256, NROWS / 32), 256>>>(out, out_b, out_W, out_b2);
    k_final_slow<<<NROWS, 256>>>(out, out_g, out_b, out_W, out_b2);
}